// round 16
// baseline (speedup 1.0000x reference)
#include <cuda_runtime.h>
#include <cstdint>

#define DD 64
#define WARPS 16
#define NPAIRS 8                // warp pairs; each pair owns a 16-edge tile
#define EPT 16                  // edges per pair tile
#define TILE_E (NPAIRS * EPT)   // 128 edges per block-tile
#define SA_STRIDE 132           // activation row stride (floats)
#define NTHREADS 512

// smem float offsets
// W1 pre-split: [64 col][132 float2] = 16896 floats
// W2,Wg pre-split: [64 col][68 float2] = 8704 floats each
#define W1_OFF 0
#define W2_OFF 16896
#define WG_OFF 25600
#define B_OFF  34304                               // b1,b2,bg (3*64)
#define A_OFF  34496                               // per-pair [16][132]
#define SMEM_FLOATS (A_OFF + NPAIRS * EPT * SA_STRIDE)
#define SMEM_BYTES (SMEM_FLOATS * 4)               // 205568 B

#define MAXE (1 << 20)
#define MAXN 65536

__device__ int g_cnt[MAXN];
__device__ int g_src[MAXE];
__device__ int g_dst[MAXE];
__device__ int g_is64;

__device__ __forceinline__ void mma_tf32(float* d, const unsigned* a, const unsigned* b) {
    asm volatile(
        "mma.sync.aligned.m16n8k8.row.col.f32.tf32.tf32.f32 "
        "{%0,%1,%2,%3}, {%4,%5,%6,%7}, {%8,%9}, {%0,%1,%2,%3};"
        : "+f"(d[0]), "+f"(d[1]), "+f"(d[2]), "+f"(d[3])
        : "r"(a[0]), "r"(a[1]), "r"(a[2]), "r"(a[3]), "r"(b[0]), "r"(b[1]));
}
// split x into tf32-exact hi + fp32 residual lo (exact: x = hi + lo)
__device__ __forceinline__ void tf32_split(float x, unsigned& hi, unsigned& lo) {
    asm("cvt.rna.tf32.f32 %0, %1;" : "=r"(hi) : "f"(x));
    lo = __float_as_uint(x - __uint_as_float(hi));
}
__device__ __forceinline__ void red_v2(float* p, float a, float b) {
    asm volatile("red.global.add.v2.f32 [%0], {%1,%2};"
                 :: "l"(p), "f"(a), "f"(b) : "memory");
}
__device__ __forceinline__ float sigmoidf(float x) {
    return __fdividef(1.0f, 1.0f + __expf(-x));
}
#define PAIR_BAR(p) asm volatile("bar.sync %0, 64;" :: "r"((p) + 1) : "memory")

__global__ void zero_kernel(float* __restrict__ out, int n_out, int n_cnt) {
    int stride = gridDim.x * blockDim.x;
    int i = blockIdx.x * blockDim.x + threadIdx.x;
    for (int j = i; j < n_out; j += stride) out[j] = 0.0f;
    for (int j = i; j < n_cnt; j += stride) g_cnt[j] = 0;
}

// int64 vs int32 detection: int64 nonneg values -> all odd int32 words zero.
__global__ void detect_kernel(const int* __restrict__ w) {
    if (threadIdx.x == 0) {
        int all_zero = 1;
        for (int i = 0; i < 64; i++)
            if (w[2 * i + 1] != 0) { all_zero = 0; break; }
        g_is64 = all_zero;
    }
}

__global__ void decode_kernel(const void* __restrict__ buf, int E, int N) {
    int i = blockIdx.x * blockDim.x + threadIdx.x;
    if (i >= E) return;
    int s, d;
    if (g_is64) {
        const long long* p = (const long long*)buf;
        s = (int)p[i]; d = (int)p[E + i];
    } else {
        const int* p = (const int*)buf;
        s = p[i]; d = p[E + i];
    }
    s = min(max(s, 0), N - 1);
    d = min(max(d, 0), N - 1);
    g_src[i] = s;
    g_dst[i] = d;
    atomicAdd(&g_cnt[s], 1);
}

__global__ __launch_bounds__(NTHREADS, 1) void mma_edge_kernel(
    const float* __restrict__ node_emb,
    const float* __restrict__ W1, const float* __restrict__ b1,
    const float* __restrict__ W2, const float* __restrict__ b2,
    const float* __restrict__ Wg, const float* __restrict__ bg,
    float* __restrict__ out, int E)
{
    extern __shared__ float smem[];
    const int tid = threadIdx.x, wid = tid >> 5, lane = tid & 31;
    const int eq = lane >> 2;     // quad (row group 0-7)
    const int qt = lane & 3;      // thread in quad
    const int pr = wid >> 1;      // warp pair 0-7
    const int role = wid & 1;     // 0: cols 0-31, 1: cols 32-63

    // ---- stage pre-split transposed weights + biases (once per CTA) ----
    // W1: [col n][k] -> float2(hi,lo) at n*264 + 2k, row stride 132 float2
    for (int i = tid; i < 64 * 128; i += NTHREADS) {
        int n = i >> 7, k = i & 127;
        unsigned hi, lo;
        tf32_split(W1[k * 64 + n], hi, lo);
        smem[W1_OFF + n * 264 + 2 * k]     = __uint_as_float(hi);
        smem[W1_OFF + n * 264 + 2 * k + 1] = __uint_as_float(lo);
    }
    for (int i = tid; i < 64 * 64; i += NTHREADS) {
        int n = i >> 6, k = i & 63;
        unsigned hi, lo;
        tf32_split(W2[k * 64 + n], hi, lo);
        smem[W2_OFF + n * 136 + 2 * k]     = __uint_as_float(hi);
        smem[W2_OFF + n * 136 + 2 * k + 1] = __uint_as_float(lo);
        tf32_split(Wg[k * 64 + n], hi, lo);
        smem[WG_OFF + n * 136 + 2 * k]     = __uint_as_float(hi);
        smem[WG_OFF + n * 136 + 2 * k + 1] = __uint_as_float(lo);
    }
    for (int i = tid; i < 64; i += NTHREADS) {
        smem[B_OFF + i]       = b1[i];
        smem[B_OFF + 64 + i]  = b2[i];
        smem[B_OFF + 128 + i] = bg[i];
    }
    __syncthreads();

    float* sA = smem + A_OFF + pr * (EPT * SA_STRIDE);
    const int cb = role * 32;      // this warp's output column base

    const int ntiles = (E + TILE_E - 1) / TILE_E;
    for (int tile = blockIdx.x; tile < ntiles; tile += gridDim.x) {
        const int base = tile * TILE_E + pr * EPT;
        if (base >= E) continue;   // both warps of a pair agree

        // ---- gather: warp role loads rows role*8..role*8+7; lanes 0-15 src, 16-31 dst ----
        {
            const int half = (lane < 16) ? 0 : 64;
            const int j = lane & 15;
            #pragma unroll
            for (int i = 0; i < 8; i++) {
                int r = role * 8 + i;
                int ei = min(base + r, E - 1);
                int node = (lane < 16) ? g_src[ei] : g_dst[ei];
                float4 v = *(const float4*)(node_emb + (size_t)node * DD + j * 4);
                *(float4*)(sA + r * SA_STRIDE + half + j * 4) = v;
            }
        }
        PAIR_BAR(pr);

        // ---- GEMM1: D1[16 x 32] = pair[16x128] @ W1t cols cb..cb+31 (16 ks, 3xTF32) ----
        float D1[4][4];
        #pragma unroll
        for (int nb = 0; nb < 4; nb++)
            D1[nb][0] = D1[nb][1] = D1[nb][2] = D1[nb][3] = 0.0f;
        #pragma unroll 2
        for (int ks = 0; ks < 16; ks++) {
            unsigned bh[4][2], bl[4][2], ah[4], al[4];
            #pragma unroll
            for (int nb = 0; nb < 4; nb++) {
                const float* wp = smem + W1_OFF + (cb + nb * 8 + eq) * 264 + (ks * 8 + qt) * 2;
                float2 w0 = *(const float2*)(wp);
                float2 w1 = *(const float2*)(wp + 8);
                bh[nb][0] = __float_as_uint(w0.x); bl[nb][0] = __float_as_uint(w0.y);
                bh[nb][1] = __float_as_uint(w1.x); bl[nb][1] = __float_as_uint(w1.y);
            }
            {
                const float* ap = sA + eq * SA_STRIDE + ks * 8 + qt;
                tf32_split(ap[0],                 ah[0], al[0]);
                tf32_split(ap[8 * SA_STRIDE],     ah[1], al[1]);
                tf32_split(ap[4],                 ah[2], al[2]);
                tf32_split(ap[8 * SA_STRIDE + 4], ah[3], al[3]);
            }
            #pragma unroll
            for (int nb = 0; nb < 4; nb++) {
                mma_tf32(D1[nb], ah, bh[nb]);
                mma_tf32(D1[nb], ah, bl[nb]);
                mma_tf32(D1[nb], al, bh[nb]);
            }
        }
        PAIR_BAR(pr);   // GEMM1 reads of sA done before h overwrite

        // ---- epilogue 1: h = relu(D1 + b1) -> sA cols cb..cb+31 ----
        #pragma unroll
        for (int nb = 0; nb < 4; nb++) {
            int c = cb + nb * 8 + 2 * qt;
            float bb0 = smem[B_OFF + c], bb1 = smem[B_OFF + c + 1];
            float2 h0 = make_float2(fmaxf(D1[nb][0] + bb0, 0.0f),
                                    fmaxf(D1[nb][1] + bb1, 0.0f));
            float2 h1 = make_float2(fmaxf(D1[nb][2] + bb0, 0.0f),
                                    fmaxf(D1[nb][3] + bb1, 0.0f));
            *(float2*)(sA + eq * SA_STRIDE + c) = h0;
            *(float2*)(sA + (eq + 8) * SA_STRIDE + c) = h1;
        }
        PAIR_BAR(pr);

        // ---- GEMM2: D2 = h @ W2t cols cb.. (8 ks, 3xTF32) ----
        float D2[4][4];
        #pragma unroll
        for (int nb = 0; nb < 4; nb++)
            D2[nb][0] = D2[nb][1] = D2[nb][2] = D2[nb][3] = 0.0f;
        #pragma unroll 2
        for (int ks = 0; ks < 8; ks++) {
            unsigned bh[4][2], bl[4][2], ah[4], al[4];
            #pragma unroll
            for (int nb = 0; nb < 4; nb++) {
                const float* wp = smem + W2_OFF + (cb + nb * 8 + eq) * 136 + (ks * 8 + qt) * 2;
                float2 w0 = *(const float2*)(wp);
                float2 w1 = *(const float2*)(wp + 8);
                bh[nb][0] = __float_as_uint(w0.x); bl[nb][0] = __float_as_uint(w0.y);
                bh[nb][1] = __float_as_uint(w1.x); bl[nb][1] = __float_as_uint(w1.y);
            }
            {
                const float* ap = sA + eq * SA_STRIDE + ks * 8 + qt;
                tf32_split(ap[0],                 ah[0], al[0]);
                tf32_split(ap[8 * SA_STRIDE],     ah[1], al[1]);
                tf32_split(ap[4],                 ah[2], al[2]);
                tf32_split(ap[8 * SA_STRIDE + 4], ah[3], al[3]);
            }
            #pragma unroll
            for (int nb = 0; nb < 4; nb++) {
                mma_tf32(D2[nb], ah, bh[nb]);
                mma_tf32(D2[nb], ah, bl[nb]);
                mma_tf32(D2[nb], al, bh[nb]);
            }
        }

        // ---- epilogue 2: t = D2 + b2 -> sA cols 64+cb.. (no overlap with h reads) ----
        #pragma unroll
        for (int nb = 0; nb < 4; nb++) {
            int c = cb + nb * 8 + 2 * qt;
            float bb0 = smem[B_OFF + 64 + c], bb1 = smem[B_OFF + 64 + c + 1];
            float2 t0 = make_float2(D2[nb][0] + bb0, D2[nb][1] + bb1);
            float2 t1 = make_float2(D2[nb][2] + bb0, D2[nb][3] + bb1);
            *(float2*)(sA + eq * SA_STRIDE + 64 + c) = t0;
            *(float2*)(sA + (eq + 8) * SA_STRIDE + 64 + c) = t1;
        }
        PAIR_BAR(pr);

        // ---- GEMM3: D3 = t @ Wgt cols cb.. (8 ks, 3xTF32) ----
        float D3[4][4];
        #pragma unroll
        for (int nb = 0; nb < 4; nb++)
            D3[nb][0] = D3[nb][1] = D3[nb][2] = D3[nb][3] = 0.0f;
        #pragma unroll 2
        for (int ks = 0; ks < 8; ks++) {
            unsigned bh[4][2], bl[4][2], ah[4], al[4];
            #pragma unroll
            for (int nb = 0; nb < 4; nb++) {
                const float* wp = smem + WG_OFF + (cb + nb * 8 + eq) * 136 + (ks * 8 + qt) * 2;
                float2 w0 = *(const float2*)(wp);
                float2 w1 = *(const float2*)(wp + 8);
                bh[nb][0] = __float_as_uint(w0.x); bl[nb][0] = __float_as_uint(w0.y);
                bh[nb][1] = __float_as_uint(w1.x); bl[nb][1] = __float_as_uint(w1.y);
            }
            {
                const float* ap = sA + eq * SA_STRIDE + 64 + ks * 8 + qt;
                tf32_split(ap[0],                 ah[0], al[0]);
                tf32_split(ap[8 * SA_STRIDE],     ah[1], al[1]);
                tf32_split(ap[4],                 ah[2], al[2]);
                tf32_split(ap[8 * SA_STRIDE + 4], ah[3], al[3]);
            }
            #pragma unroll
            for (int nb = 0; nb < 4; nb++) {
                mma_tf32(D3[nb], ah, bh[nb]);
                mma_tf32(D3[nb], ah, bl[nb]);
                mma_tf32(D3[nb], al, bh[nb]);
            }
        }

        // ---- epilogue 3: gated = t * sigmoid(D3 + bg); scatter cols cb..cb+31 ----
        {
            int e0 = base + eq, e1 = base + eq + 8;
            bool v0 = e0 < E, v1 = e1 < E;
            int s0 = g_src[min(e0, E - 1)];
            int s1 = g_src[min(e1, E - 1)];
            #pragma unroll
            for (int nb = 0; nb < 4; nb++) {
                int c = cb + nb * 8 + 2 * qt;
                float bg0 = smem[B_OFF + 128 + c], bg1 = smem[B_OFF + 128 + c + 1];
                float2 t0 = *(const float2*)(sA + eq * SA_STRIDE + 64 + c);
                float2 t1 = *(const float2*)(sA + (eq + 8) * SA_STRIDE + 64 + c);
                if (v0) {
                    float ga = sigmoidf(D3[nb][0] + bg0);
                    float gb = sigmoidf(D3[nb][1] + bg1);
                    red_v2(out + (size_t)s0 * DD + c, t0.x * ga, t0.y * gb);
                }
                if (v1) {
                    float ga = sigmoidf(D3[nb][2] + bg0);
                    float gb = sigmoidf(D3[nb][3] + bg1);
                    red_v2(out + (size_t)s1 * DD + c, t1.x * ga, t1.y * gb);
                }
            }
        }
        PAIR_BAR(pr);   // sA reuse safety before next tile's gather
    }
}

__global__ void norm_kernel(float* __restrict__ out, int n_out) {
    int i = blockIdx.x * blockDim.x + threadIdx.x;
    if (i < n_out) {
        float c = (float)g_cnt[i >> 6];
        out[i] = out[i] / fmaxf(c, 1.0f);
    }
}

extern "C" void kernel_launch(void* const* d_in, const int* in_sizes, int n_in,
                              void* d_out, int out_size)
{
    const float* node_emb = (const float*)d_in[0];
    const void*  ei       = d_in[1];
    const float* W1       = (const float*)d_in[2];
    const float* b1       = (const float*)d_in[3];
    const float* W2       = (const float*)d_in[4];
    const float* b2       = (const float*)d_in[5];
    const float* Wg       = (const float*)d_in[6];
    const float* bg       = (const float*)d_in[7];
    float*       out      = (float*)d_out;

    const int N = in_sizes[0] / DD;
    const int E = in_sizes[1] / 2;

    zero_kernel<<<256, 256>>>(out, N * DD, N);
    detect_kernel<<<1, 32>>>((const int*)ei);
    decode_kernel<<<(E + 255) / 256, 256>>>(ei, E, N);

    cudaFuncSetAttribute(mma_edge_kernel,
                         cudaFuncAttributeMaxDynamicSharedMemorySize, SMEM_BYTES);
    mma_edge_kernel<<<148, NTHREADS, SMEM_BYTES>>>(node_emb,
                                                   W1, b1, W2, b2, Wg, bg, out, E);

    norm_kernel<<<(N * DD + 255) / 256, 256>>>(out, N * DD);
}

// round 17
// speedup vs baseline: 2.5789x; 2.5789x over previous
#include <cuda_runtime.h>
#include <cstdint>

#define DD 64
#define WARPS 16
#define EPT 16                  // edges per warp tile
#define TILE_E (WARPS * EPT)    // 256 edges per block-tile
#define SA_STRIDE 132           // activation row stride (floats)
#define NTHREADS 512

// smem layout. Weight planes are u32 (bf16x2 k-pairs), act staging is f32.
// u32/float offsets into the shared buffer:
#define W1H_OFF 0                       // [64 n][68]  (64 kpairs + pad)
#define W1L_OFF 4352
#define W2H_OFF 8704                    // [64 n][36]  (32 kpairs + pad)
#define W2L_OFF 11008
#define WGH_OFF 13312
#define WGL_OFF 15616
#define B_OFF   17920                   // b1,b2,bg (3*64 f32)
#define A_OFF   18112                   // per-warp [16][132] f32
#define SMEM_FLOATS (A_OFF + WARPS * EPT * SA_STRIDE)
#define SMEM_BYTES (SMEM_FLOATS * 4)    // 207616 B

#define MAXE (1 << 20)
#define MAXN 65536

__device__ int g_cnt[MAXN];
__device__ int g_src[MAXE];
__device__ int g_dst[MAXE];
__device__ int g_is64;

__device__ __forceinline__ void mma_bf16(float* d, const unsigned* a, const unsigned* b) {
    asm volatile(
        "mma.sync.aligned.m16n8k16.row.col.f32.bf16.bf16.f32 "
        "{%0,%1,%2,%3}, {%4,%5,%6,%7}, {%8,%9}, {%0,%1,%2,%3};"
        : "+f"(d[0]), "+f"(d[1]), "+f"(d[2]), "+f"(d[3])
        : "r"(a[0]), "r"(a[1]), "r"(a[2]), "r"(a[3]), "r"(b[0]), "r"(b[1]));
}
// split float pair (x.x = even k -> low half, x.y = odd k -> high half) into
// bf16x2 hi + bf16x2 lo.  Residuals are exact in fp32 (Sterbenz).
__device__ __forceinline__ void bf16_split2(float2 x, unsigned& hi, unsigned& lo) {
    asm("cvt.rn.bf16x2.f32 %0, %1, %2;" : "=r"(hi) : "f"(x.y), "f"(x.x));
    float h0 = __uint_as_float(hi << 16);
    float h1 = __uint_as_float(hi & 0xFFFF0000u);
    float r0 = x.x - h0;
    float r1 = x.y - h1;
    asm("cvt.rn.bf16x2.f32 %0, %1, %2;" : "=r"(lo) : "f"(r1), "f"(r0));
}
__device__ __forceinline__ void red_v2(float* p, float a, float b) {
    asm volatile("red.global.add.v2.f32 [%0], {%1,%2};"
                 :: "l"(p), "f"(a), "f"(b) : "memory");
}
__device__ __forceinline__ float sigmoidf(float x) {
    return __fdividef(1.0f, 1.0f + __expf(-x));
}

__global__ void zero_kernel(float* __restrict__ out, int n_out, int n_cnt) {
    int stride = gridDim.x * blockDim.x;
    int i = blockIdx.x * blockDim.x + threadIdx.x;
    for (int j = i; j < n_out; j += stride) out[j] = 0.0f;
    for (int j = i; j < n_cnt; j += stride) g_cnt[j] = 0;
}

// int64 vs int32 detection: int64 nonneg values -> all odd int32 words zero.
__global__ void detect_kernel(const int* __restrict__ w) {
    if (threadIdx.x == 0) {
        int all_zero = 1;
        for (int i = 0; i < 64; i++)
            if (w[2 * i + 1] != 0) { all_zero = 0; break; }
        g_is64 = all_zero;
    }
}

__global__ void decode_kernel(const void* __restrict__ buf, int E, int N) {
    int i = blockIdx.x * blockDim.x + threadIdx.x;
    if (i >= E) return;
    int s, d;
    if (g_is64) {
        const long long* p = (const long long*)buf;
        s = (int)p[i]; d = (int)p[E + i];
    } else {
        const int* p = (const int*)buf;
        s = p[i]; d = p[E + i];
    }
    s = min(max(s, 0), N - 1);
    d = min(max(d, 0), N - 1);
    g_src[i] = s;
    g_dst[i] = d;
    atomicAdd(&g_cnt[s], 1);
}

__global__ __launch_bounds__(NTHREADS, 1) void mma_edge_kernel(
    const float* __restrict__ node_emb,
    const float* __restrict__ W1, const float* __restrict__ b1,
    const float* __restrict__ W2, const float* __restrict__ b2,
    const float* __restrict__ Wg, const float* __restrict__ bg,
    float* __restrict__ out, int E)
{
    extern __shared__ float smem[];
    unsigned* smemu = (unsigned*)smem;
    const int tid = threadIdx.x, wid = tid >> 5, lane = tid & 31;
    const int eq = lane >> 2;     // quad (row group 0-7)
    const int qt = lane & 3;      // thread in quad

    // ---- stage pre-split transposed weights as bf16x2 k-pair planes ----
    // W1: n in [0,64), kpair in [0,64): plane[n*68 + kp]
    for (int i = tid; i < 64 * 64; i += NTHREADS) {
        int n = i >> 6, kp = i & 63;
        float2 w = make_float2(W1[(2 * kp) * 64 + n], W1[(2 * kp + 1) * 64 + n]);
        unsigned hi, lo;
        bf16_split2(w, hi, lo);
        smemu[W1H_OFF + n * 68 + kp] = hi;
        smemu[W1L_OFF + n * 68 + kp] = lo;
    }
    // W2, Wg: kpair in [0,32): plane[n*36 + kp]
    for (int i = tid; i < 64 * 32; i += NTHREADS) {
        int n = i >> 5, kp = i & 31;
        unsigned hi, lo;
        float2 w2 = make_float2(W2[(2 * kp) * 64 + n], W2[(2 * kp + 1) * 64 + n]);
        bf16_split2(w2, hi, lo);
        smemu[W2H_OFF + n * 36 + kp] = hi;
        smemu[W2L_OFF + n * 36 + kp] = lo;
        float2 wg = make_float2(Wg[(2 * kp) * 64 + n], Wg[(2 * kp + 1) * 64 + n]);
        bf16_split2(wg, hi, lo);
        smemu[WGH_OFF + n * 36 + kp] = hi;
        smemu[WGL_OFF + n * 36 + kp] = lo;
    }
    for (int i = tid; i < 64; i += NTHREADS) {
        smem[B_OFF + i]       = b1[i];
        smem[B_OFF + 64 + i]  = b2[i];
        smem[B_OFF + 128 + i] = bg[i];
    }
    __syncthreads();

    float* sA = smem + A_OFF + wid * (EPT * SA_STRIDE);

    const int ntiles = (E + TILE_E - 1) / TILE_E;
    for (int tile = blockIdx.x; tile < ntiles; tile += gridDim.x) {
        const int base = tile * TILE_E + wid * EPT;
        if (base >= E) continue;

        // ---- gather pair embeddings: lanes 0-15 src half, 16-31 dst ----
        {
            const int half = (lane < 16) ? 0 : 64;
            const int j = lane & 15;
            #pragma unroll 4
            for (int i = 0; i < EPT; i++) {
                int ei = min(base + i, E - 1);
                int node = (lane < 16) ? g_src[ei] : g_dst[ei];
                float4 v = *(const float4*)(node_emb + (size_t)node * DD + j * 4);
                *(float4*)(sA + i * SA_STRIDE + half + j * 4) = v;
            }
        }
        __syncwarp();

        // ---- GEMM1: D1[16x64] = pair[16x128] @ W1t  (8 k16-steps, bf16x3) ----
        float D1[8][4];
        #pragma unroll
        for (int nb = 0; nb < 8; nb++)
            D1[nb][0] = D1[nb][1] = D1[nb][2] = D1[nb][3] = 0.0f;
        #pragma unroll 2
        for (int ks = 0; ks < 8; ks++) {
            unsigned bh[8][2], bl[8][2], ah[4], al[4];
            #pragma unroll
            for (int nb = 0; nb < 8; nb++) {
                const unsigned* wh = smemu + W1H_OFF + (nb * 8 + eq) * 68 + ks * 8 + qt;
                const unsigned* wl = smemu + W1L_OFF + (nb * 8 + eq) * 68 + ks * 8 + qt;
                bh[nb][0] = wh[0]; bh[nb][1] = wh[4];
                bl[nb][0] = wl[0]; bl[nb][1] = wl[4];
            }
            {
                const float* ap = sA + eq * SA_STRIDE + ks * 16 + qt * 2;
                bf16_split2(*(const float2*)(ap),                     ah[0], al[0]);
                bf16_split2(*(const float2*)(ap + 8 * SA_STRIDE),     ah[1], al[1]);
                bf16_split2(*(const float2*)(ap + 8),                 ah[2], al[2]);
                bf16_split2(*(const float2*)(ap + 8 * SA_STRIDE + 8), ah[3], al[3]);
            }
            #pragma unroll
            for (int nb = 0; nb < 8; nb++) {
                mma_bf16(D1[nb], ah, bh[nb]);
                mma_bf16(D1[nb], ah, bl[nb]);
                mma_bf16(D1[nb], al, bh[nb]);
            }
        }
        __syncwarp();

        // ---- epilogue 1: h = relu(D1 + b1) -> sA cols 0..63 ----
        #pragma unroll
        for (int nb = 0; nb < 8; nb++) {
            int c = nb * 8 + 2 * qt;
            float bb0 = smem[B_OFF + c], bb1 = smem[B_OFF + c + 1];
            float2 h0 = make_float2(fmaxf(D1[nb][0] + bb0, 0.0f),
                                    fmaxf(D1[nb][1] + bb1, 0.0f));
            float2 h1 = make_float2(fmaxf(D1[nb][2] + bb0, 0.0f),
                                    fmaxf(D1[nb][3] + bb1, 0.0f));
            *(float2*)(sA + eq * SA_STRIDE + c) = h0;
            *(float2*)(sA + (eq + 8) * SA_STRIDE + c) = h1;
        }
        __syncwarp();

        // ---- GEMM2: D2 = h @ W2t  (4 k16-steps, bf16x3) ----
        float D2[8][4];
        #pragma unroll
        for (int nb = 0; nb < 8; nb++)
            D2[nb][0] = D2[nb][1] = D2[nb][2] = D2[nb][3] = 0.0f;
        #pragma unroll 2
        for (int ks = 0; ks < 4; ks++) {
            unsigned bh[8][2], bl[8][2], ah[4], al[4];
            #pragma unroll
            for (int nb = 0; nb < 8; nb++) {
                const unsigned* wh = smemu + W2H_OFF + (nb * 8 + eq) * 36 + ks * 8 + qt;
                const unsigned* wl = smemu + W2L_OFF + (nb * 8 + eq) * 36 + ks * 8 + qt;
                bh[nb][0] = wh[0]; bh[nb][1] = wh[4];
                bl[nb][0] = wl[0]; bl[nb][1] = wl[4];
            }
            {
                const float* ap = sA + eq * SA_STRIDE + ks * 16 + qt * 2;
                bf16_split2(*(const float2*)(ap),                     ah[0], al[0]);
                bf16_split2(*(const float2*)(ap + 8 * SA_STRIDE),     ah[1], al[1]);
                bf16_split2(*(const float2*)(ap + 8),                 ah[2], al[2]);
                bf16_split2(*(const float2*)(ap + 8 * SA_STRIDE + 8), ah[3], al[3]);
            }
            #pragma unroll
            for (int nb = 0; nb < 8; nb++) {
                mma_bf16(D2[nb], ah, bh[nb]);
                mma_bf16(D2[nb], ah, bl[nb]);
                mma_bf16(D2[nb], al, bh[nb]);
            }
        }
        __syncwarp();

        // ---- epilogue 2: t = D2 + b2 -> sA cols 64..127 ----
        #pragma unroll
        for (int nb = 0; nb < 8; nb++) {
            int c = nb * 8 + 2 * qt;
            float bb0 = smem[B_OFF + 64 + c], bb1 = smem[B_OFF + 64 + c + 1];
            float2 t0 = make_float2(D2[nb][0] + bb0, D2[nb][1] + bb1);
            float2 t1 = make_float2(D2[nb][2] + bb0, D2[nb][3] + bb1);
            *(float2*)(sA + eq * SA_STRIDE + 64 + c) = t0;
            *(float2*)(sA + (eq + 8) * SA_STRIDE + 64 + c) = t1;
        }
        __syncwarp();

        // ---- GEMM3: D3 = t @ Wgt  (4 k16-steps, bf16x3) ----
        float D3[8][4];
        #pragma unroll
        for (int nb = 0; nb < 8; nb++)
            D3[nb][0] = D3[nb][1] = D3[nb][2] = D3[nb][3] = 0.0f;
        #pragma unroll 2
        for (int ks = 0; ks < 4; ks++) {
            unsigned bh[8][2], bl[8][2], ah[4], al[4];
            #pragma unroll
            for (int nb = 0; nb < 8; nb++) {
                const unsigned* wh = smemu + WGH_OFF + (nb * 8 + eq) * 36 + ks * 8 + qt;
                const unsigned* wl = smemu + WGL_OFF + (nb * 8 + eq) * 36 + ks * 8 + qt;
                bh[nb][0] = wh[0]; bh[nb][1] = wh[4];
                bl[nb][0] = wl[0]; bl[nb][1] = wl[4];
            }
            {
                const float* ap = sA + eq * SA_STRIDE + 64 + ks * 16 + qt * 2;
                bf16_split2(*(const float2*)(ap),                     ah[0], al[0]);
                bf16_split2(*(const float2*)(ap + 8 * SA_STRIDE),     ah[1], al[1]);
                bf16_split2(*(const float2*)(ap + 8),                 ah[2], al[2]);
                bf16_split2(*(const float2*)(ap + 8 * SA_STRIDE + 8), ah[3], al[3]);
            }
            #pragma unroll
            for (int nb = 0; nb < 8; nb++) {
                mma_bf16(D3[nb], ah, bh[nb]);
                mma_bf16(D3[nb], ah, bl[nb]);
                mma_bf16(D3[nb], al, bh[nb]);
            }
        }

        // ---- epilogue 3: gated = t * sigmoid(D3 + bg); scatter-add to src rows ----
        {
            int e0 = base + eq, e1 = base + eq + 8;
            bool v0 = e0 < E, v1 = e1 < E;
            int s0 = g_src[min(e0, E - 1)];
            int s1 = g_src[min(e1, E - 1)];
            #pragma unroll
            for (int nb = 0; nb < 8; nb++) {
                int c = nb * 8 + 2 * qt;
                float bg0 = smem[B_OFF + 128 + c], bg1 = smem[B_OFF + 128 + c + 1];
                float2 t0 = *(const float2*)(sA + eq * SA_STRIDE + 64 + c);
                float2 t1 = *(const float2*)(sA + (eq + 8) * SA_STRIDE + 64 + c);
                if (v0) {
                    float ga = sigmoidf(D3[nb][0] + bg0);
                    float gb = sigmoidf(D3[nb][1] + bg1);
                    red_v2(out + (size_t)s0 * DD + c, t0.x * ga, t0.y * gb);
                }
                if (v1) {
                    float ga = sigmoidf(D3[nb][2] + bg0);
                    float gb = sigmoidf(D3[nb][3] + bg1);
                    red_v2(out + (size_t)s1 * DD + c, t1.x * ga, t1.y * gb);
                }
            }
        }
        __syncwarp();   // sA reuse safety before next tile's gather
    }
}

__global__ void norm_kernel(float* __restrict__ out, int n_out) {
    int i = blockIdx.x * blockDim.x + threadIdx.x;
    if (i < n_out) {
        float c = (float)g_cnt[i >> 6];
        out[i] = out[i] / fmaxf(c, 1.0f);
    }
}

extern "C" void kernel_launch(void* const* d_in, const int* in_sizes, int n_in,
                              void* d_out, int out_size)
{
    const float* node_emb = (const float*)d_in[0];
    const void*  ei       = d_in[1];
    const float* W1       = (const float*)d_in[2];
    const float* b1       = (const float*)d_in[3];
    const float* W2       = (const float*)d_in[4];
    const float* b2       = (const float*)d_in[5];
    const float* Wg       = (const float*)d_in[6];
    const float* bg       = (const float*)d_in[7];
    float*       out      = (float*)d_out;

    const int N = in_sizes[0] / DD;
    const int E = in_sizes[1] / 2;

    zero_kernel<<<256, 256>>>(out, N * DD, N);
    detect_kernel<<<1, 32>>>((const int*)ei);
    decode_kernel<<<(E + 255) / 256, 256>>>(ei, E, N);

    cudaFuncSetAttribute(mma_edge_kernel,
                         cudaFuncAttributeMaxDynamicSharedMemorySize, SMEM_BYTES);
    mma_edge_kernel<<<148, NTHREADS, SMEM_BYTES>>>(node_emb,
                                                   W1, b1, W2, b2, Wg, bg, out, E);

    norm_kernel<<<(N * DD + 255) / 256, 256>>>(out, N * DD);
}